// round 8
// baseline (speedup 1.0000x reference)
#include <cuda_runtime.h>
#include <cuda_fp16.h>
#include <math.h>

#define BB 128
#define CC 64
#define HH 134
#define WW 20
#define HWS 2680
#define NK 335
#define EPSV 1e-8f

__device__ __align__(16) __half g_h [(size_t)BB*CC*HWS];   // relu(conv(x)) [b][c][hw]
__device__ __align__(16) __half g_h1[(size_t)BB*HWS*CC];   // h*ca          [b][hw][c]
__device__ float g_ca [BB*CC];
__device__ float g_sp [BB*2*HWS];
__device__ float g_sa [BB*HWS];
__device__ float g_S  [BB*8];
__device__ float g_T  [2*BB*8];
__device__ float g_a  [BB*16];
__device__ float g_d  [BB*8];

// conv3x3 + relu + per-(b,c) sum/max + CBAM channel-attention MLP, fused.
// grid(BB) x 256; warp w owns channels [8w, 8w+8); block owns batch b entirely.
__global__ __launch_bounds__(256) void k_conv(const float* __restrict__ x,
                                              const float* __restrict__ cw,
                                              const float* __restrict__ cb,
                                              const float* __restrict__ w1,
                                              const float* __restrict__ w2) {
    int b = blockIdx.x;
    __shared__ float tile[136 * 22];                // full image + 1-halo
    __shared__ float avg[64], mxv[64], hid[8];
    const float* xb = x + b * HWS;
    for (int i = threadIdx.x; i < 136 * 22; i += 256) {
        int rr = i / 22 - 1, cc = i % 22 - 1;
        tile[i] = (rr >= 0 && rr < HH && cc >= 0 && cc < WW) ? xb[rr * WW + cc] : 0.f;
    }
    __syncthreads();
    int warp = threadIdx.x >> 5, lane = threadIdx.x & 31, c0 = warp * 8;
    float w[8][9], bias[8], sum[8], mx[8];
#pragma unroll
    for (int j = 0; j < 8; j++) {
#pragma unroll
        for (int t = 0; t < 9; t++) w[j][t] = __ldg(&cw[(c0 + j) * 9 + t]);
        bias[j] = __ldg(&cb[c0 + j]);
        sum[j] = 0.f; mx[j] = 0.f;
    }
    for (int p = lane; p < HWS; p += 32) {
        int lr = p / WW, col = p % WW;
        float win[9];
#pragma unroll
        for (int dr = 0; dr < 3; dr++)
#pragma unroll
            for (int dc = 0; dc < 3; dc++) win[dr * 3 + dc] = tile[(lr + dr) * 22 + col + dc];
#pragma unroll
        for (int j = 0; j < 8; j++) {
            float acc = bias[j];
#pragma unroll
            for (int t = 0; t < 9; t++) acc = fmaf(w[j][t], win[t], acc);
            acc = fmaxf(acc, 0.f);
            g_h[((size_t)b * CC + c0 + j) * HWS + p] = __float2half(acc);
            sum[j] += acc; mx[j] = fmaxf(mx[j], acc);
        }
    }
#pragma unroll
    for (int j = 0; j < 8; j++)
#pragma unroll
        for (int o = 16; o > 0; o >>= 1) {
            sum[j] += __shfl_xor_sync(~0u, sum[j], o);
            mx[j] = fmaxf(mx[j], __shfl_xor_sync(~0u, mx[j], o));
        }
    if (lane == 0)
#pragma unroll
        for (int j = 0; j < 8; j++) {
            avg[c0 + j] = sum[j] * (1.f / HWS);
            mxv[c0 + j] = mx[j];
        }
    __syncthreads();
    // CBAM channel MLP: hidden dim 4, shared across avg/max paths
    int t = threadIdx.x;
    if (t < 8) {
        const float* v = (t < 4) ? avg : mxv;
        int i = t & 3;
        float acc = 0.f;
        for (int c = 0; c < 64; c++) acc += v[c] * __ldg(&w1[i * 64 + c]);
        hid[t] = fmaxf(acc, 0.f);
    }
    __syncthreads();
    if (t < 64) {
        float o = 0.f;
#pragma unroll
        for (int i = 0; i < 4; i++) o += (hid[i] + hid[4 + i]) * __ldg(&w2[t * 4 + i]);
        g_ca[b * 64 + t] = 1.f / (1.f + __expf(-o));
    }
}

// apply ca; per-pixel channel mean/max; write h1 transposed. grid(42, BB) x 256
__global__ __launch_bounds__(256) void k_spatial() {
    int b = blockIdx.y, p0 = blockIdx.x * 64;
    int np = min(64, HWS - p0);
    __shared__ float tile[64 * 65];
    for (int i = threadIdx.x; i < 64 * 64; i += 256) {
        int c = i >> 6, p = i & 63;
        float v = 0.f;
        if (p < np)
            v = __half2float(g_h[((size_t)b * CC + c) * HWS + p0 + p]) * g_ca[b * 64 + c];
        tile[c * 65 + p] = v;
    }
    __syncthreads();
    if (threadIdx.x < 64) {
        int p = threadIdx.x;
        if (p < np) {
            float s = 0.f, m = 0.f;
            for (int c = 0; c < 64; c++) { float v = tile[c * 65 + p]; s += v; m = fmaxf(m, v); }
            g_sp[(b * 2 + 0) * HWS + p0 + p] = s * (1.f / 64.f);
            g_sp[(b * 2 + 1) * HWS + p0 + p] = m;
        }
    }
    for (int i = threadIdx.x; i < 64 * 64; i += 256) {
        int p = i >> 6, c = i & 63;
        if (p < np)
            g_h1[((size_t)b * HWS + p0 + p) * 64 + c] = __float2half(tile[c * 65 + p]);
    }
}

// 7x7 spatial-attn conv + sigmoid; accumulate S_e.  grid(BB) x 256
__global__ __launch_bounds__(256) void k_saconv(const float* __restrict__ sw) {
    int b = blockIdx.x;
    __shared__ float tile[2 * 140 * 26];
    __shared__ float wts[98];
    __shared__ float red[256];
    if (threadIdx.x < 98) wts[threadIdx.x] = sw[threadIdx.x];
    for (int i = threadIdx.x; i < 2 * 140 * 26; i += 256) {
        int ch = i / (140 * 26), rem = i % (140 * 26);
        int rr = rem / 26 - 3, cc = rem % 26 - 3;
        float v = 0.f;
        if (rr >= 0 && rr < HH && cc >= 0 && cc < WW)
            v = g_sp[(b * 2 + ch) * HWS + rr * WW + cc];
        tile[i] = v;
    }
    __syncthreads();
    float Sacc = 0.f;
    for (int p = threadIdx.x; p < HWS; p += 256) {
        int r = p / WW, c = p % WW;
        float acc = 0.f;
#pragma unroll
        for (int ch = 0; ch < 2; ch++)
            for (int dr = 0; dr < 7; dr++)
#pragma unroll
                for (int dc = 0; dc < 7; dc++)
                    acc = fmaf(wts[ch * 49 + dr * 7 + dc],
                               tile[ch * 140 * 26 + (r + dr) * 26 + c + dc], acc);
        float sa = 1.f / (1.f + __expf(-acc));
        g_sa[b * HWS + p] = sa;
        Sacc += sa * tile[(r + 3) * 26 + c + 3];   // sp_mean at p (ch 0 center)
    }
    red[threadIdx.x] = Sacc;
    __syncthreads();
    if (threadIdx.x < 8) {
        float s = 0.f;
        for (int i = threadIdx.x; i < 256; i += 8) s += red[i];   // p%8 == tid%8
        g_S[b * 8 + threadIdx.x] = s * 64.f;
    }
}

// routing math for one iteration; also zeroes g_T slice `phase` for the
// following k_tpass accumulation (distinct from the slice it reads).
// grid(BB) x 32
__global__ __launch_bounds__(32) void k_math(const float* __restrict__ cW,
                                             float* __restrict__ out, int phase) {
    int b = blockIdx.x, t = threadIdx.x, j = t >> 4;
    if (phase < 2 && t < 8) g_T[phase * BB * 8 + b * 8 + t] = 0.f;
    float Wc[8];
#pragma unroll
    for (int e = 0; e < 8; e++) Wc[e] = cW[e * 32 + t];
    float te[8];
#pragma unroll
    for (int e = 0; e < 8; e++) {
        float S = g_S[b * 8 + e];
        if (phase == 0) te[e] = 0.5f * S;
        else {
            float T = g_T[(phase - 1) * BB * 8 + b * 8 + e];
            te[e] = (j == 0) ? T : S - T;
        }
    }
    float s = 0.f;
#pragma unroll
    for (int e = 0; e < 8; e++) s = fmaf(te[e], Wc[e], s);
    float ss = s * s;
#pragma unroll
    for (int o = 8; o > 0; o >>= 1) ss += __shfl_xor_sync(~0u, ss, o);
    ss += EPSV;
    float scale = sqrtf(ss) / (1.f + ss);
    float v = scale * s;
    if (phase < 2) {
        __shared__ float sa_[16];
#pragma unroll
        for (int e = 0; e < 8; e++) {
            float pa = Wc[e] * v;
#pragma unroll
            for (int o = 8; o > 0; o >>= 1) pa += __shfl_xor_sync(~0u, pa, o);
            if ((t & 15) == e) {
                float an = pa;
                if (phase == 1) an += g_a[b * 16 + j * 8 + e];
                g_a[b * 16 + j * 8 + e] = an;
                sa_[j * 8 + e] = an;
            }
        }
        __syncwarp();
        if (t < 8) g_d[b * 8 + t] = sa_[t] - sa_[8 + t];
    } else {
        float vs = v * v;
#pragma unroll
        for (int o = 8; o > 0; o >>= 1) vs += __shfl_xor_sync(~0u, vs, o);
        if ((t & 15) == 0) out[b * 2 + j] = sqrtf(vs + EPSV);
    }
}

// T_e = sum_n sigmoid(u_n . d) u_{n,e}.  grid(4, BB) x 256
__global__ __launch_bounds__(256) void k_tpass(int pass) {
    int b = blockIdx.y;
    int k0 = blockIdx.x * 84, kend = min(k0 + 84, NK);
    int warp = threadIdx.x >> 5, lane = threadIdx.x & 31;
    float d[8], Te[8];
#pragma unroll
    for (int e = 0; e < 8; e++) { d[e] = g_d[b * 8 + e]; Te[e] = 0.f; }
    const __half2* h1b = (const __half2*)(g_h1 + (size_t)b * HWS * 64);
    const float* sab = g_sa + b * HWS;
    for (int k = k0 + warp; k < kend; k += 8) {
        float ux[8], uy[8], dx = 0.f, dy = 0.f;
#pragma unroll
        for (int e = 0; e < 8; e++) {
            float sae = __ldg(&sab[8 * k + e]);
            float2 f = __half22float2(h1b[(8 * k + e) * 32 + lane]);
            ux[e] = f.x * sae; uy[e] = f.y * sae;
            dx = fmaf(ux[e], d[e], dx);
            dy = fmaf(uy[e], d[e], dy);
        }
        float sx = 1.f / (1.f + __expf(-dx));
        float sy = 1.f / (1.f + __expf(-dy));
#pragma unroll
        for (int e = 0; e < 8; e++) Te[e] = fmaf(sx, ux[e], fmaf(sy, uy[e], Te[e]));
    }
#pragma unroll
    for (int e = 0; e < 8; e++)
#pragma unroll
        for (int o = 16; o > 0; o >>= 1) Te[e] += __shfl_xor_sync(~0u, Te[e], o);
    if (lane == 0)
#pragma unroll
        for (int e = 0; e < 8; e++)
            atomicAdd(&g_T[pass * BB * 8 + b * 8 + e], Te[e]);
}

extern "C" void kernel_launch(void* const* d_in, const int* in_sizes, int n_in,
                              void* d_out, int out_size) {
    const float* x   = (const float*)d_in[0];
    const float* cw  = (const float*)d_in[1];
    const float* cb  = (const float*)d_in[2];
    const float* w1  = (const float*)d_in[3];
    const float* w2  = (const float*)d_in[4];
    const float* sw  = (const float*)d_in[5];
    const float* cpW = (const float*)d_in[6];
    float* out = (float*)d_out;

    k_conv<<<BB, 256>>>(x, cw, cb, w1, w2);
    k_spatial<<<dim3(42, BB), 256>>>();
    k_saconv<<<BB, 256>>>(sw);
    k_math<<<BB, 32>>>(cpW, out, 0);
    k_tpass<<<dim3(4, BB), 256>>>(0);
    k_math<<<BB, 32>>>(cpW, out, 1);
    k_tpass<<<dim3(4, BB), 256>>>(1);
    k_math<<<BB, 32>>>(cpW, out, 2);
}

// round 12
// speedup vs baseline: 1.4052x; 1.4052x over previous
#include <cuda_runtime.h>
#include <cuda_fp16.h>
#include <math.h>

#define BB 128
#define CC 64
#define HH 134
#define WW 20
#define HWS 2680
#define NK 335
#define EPSV 1e-8f

__device__ __align__(16) __half g_h[(size_t)BB*CC*HWS];  // relu(conv(x)) [b][c][hw]
__device__ float g_ca[BB*CC];
__device__ float g_sa[BB*HWS];
__device__ float g_S [BB*8];
__device__ float g_T0[BB*8];

// conv3x3 + relu + per-(b,c) sum/max + CBAM channel-attention MLP, fused.
// grid(BB) x 256; warp w owns channels [8w, 8w+8); block owns batch b entirely.
__global__ __launch_bounds__(256) void k_conv(const float* __restrict__ x,
                                              const float* __restrict__ cw,
                                              const float* __restrict__ cb,
                                              const float* __restrict__ w1,
                                              const float* __restrict__ w2) {
    int b = blockIdx.x;
    __shared__ float tile[136 * 22];                // full image + 1-halo
    __shared__ float avg[64], mxv[64], hid[8];
    const float* xb = x + b * HWS;
    for (int i = threadIdx.x; i < 136 * 22; i += 256) {
        int rr = i / 22 - 1, cc = i % 22 - 1;
        tile[i] = (rr >= 0 && rr < HH && cc >= 0 && cc < WW) ? xb[rr * WW + cc] : 0.f;
    }
    __syncthreads();
    int warp = threadIdx.x >> 5, lane = threadIdx.x & 31, c0 = warp * 8;
    float w[8][9], bias[8], sum[8], mx[8];
#pragma unroll
    for (int j = 0; j < 8; j++) {
#pragma unroll
        for (int t = 0; t < 9; t++) w[j][t] = __ldg(&cw[(c0 + j) * 9 + t]);
        bias[j] = __ldg(&cb[c0 + j]);
        sum[j] = 0.f; mx[j] = 0.f;
    }
    for (int p = lane; p < HWS; p += 32) {
        int lr = p / WW, col = p % WW;
        float win[9];
#pragma unroll
        for (int dr = 0; dr < 3; dr++)
#pragma unroll
            for (int dc = 0; dc < 3; dc++) win[dr * 3 + dc] = tile[(lr + dr) * 22 + col + dc];
#pragma unroll
        for (int j = 0; j < 8; j++) {
            float acc = bias[j];
#pragma unroll
            for (int t = 0; t < 9; t++) acc = fmaf(w[j][t], win[t], acc);
            acc = fmaxf(acc, 0.f);
            g_h[((size_t)b * CC + c0 + j) * HWS + p] = __float2half(acc);
            sum[j] += acc; mx[j] = fmaxf(mx[j], acc);
        }
    }
#pragma unroll
    for (int j = 0; j < 8; j++)
#pragma unroll
        for (int o = 16; o > 0; o >>= 1) {
            sum[j] += __shfl_xor_sync(~0u, sum[j], o);
            mx[j] = fmaxf(mx[j], __shfl_xor_sync(~0u, mx[j], o));
        }
    if (lane == 0)
#pragma unroll
        for (int j = 0; j < 8; j++) {
            avg[c0 + j] = sum[j] * (1.f / HWS);
            mxv[c0 + j] = mx[j];
        }
    __syncthreads();
    int t = threadIdx.x;
    if (t < 8) {
        const float* v = (t < 4) ? avg : mxv;
        int i = t & 3;
        float acc = 0.f;
        for (int c = 0; c < 64; c++) acc += v[c] * __ldg(&w1[i * 64 + c]);
        hid[t] = fmaxf(acc, 0.f);
    }
    __syncthreads();
    if (t < 64) {
        float o = 0.f;
#pragma unroll
        for (int i = 0; i < 4; i++) o += (hid[i] + hid[4 + i]) * __ldg(&w2[t * 4 + i]);
        g_ca[b * 64 + t] = 1.f / (1.f + __expf(-o));
    }
}

// per-pixel channel mean/max of h*ca (into padded smem tile) + 7x7 conv +
// sigmoid -> g_sa; accumulate S_e.  grid(BB) x 256
__global__ __launch_bounds__(256) void k_spa(const float* __restrict__ sw) {
    int b = blockIdx.x;
    __shared__ float tile[2 * 140 * 26];
    __shared__ float wts[98];
    __shared__ float cas[64];
    __shared__ float red[256];
    int tid = threadIdx.x;
    if (tid < 98) wts[tid] = sw[tid];
    if (tid < 64) cas[tid] = g_ca[b * 64 + tid];
    for (int i = tid; i < 2 * 140 * 26; i += 256) tile[i] = 0.f;
    __syncthreads();
    // channel mean/max per pixel, 2 pixels per thread via half2
    const __half2* hb = (const __half2*)(g_h + (size_t)b * CC * HWS);
    for (int idx = tid; idx < HWS / 2; idx += 256) {
        float s0 = 0.f, s1 = 0.f, m0 = 0.f, m1 = 0.f;
#pragma unroll 8
        for (int c = 0; c < 64; c++) {
            float2 f = __half22float2(hb[c * (HWS / 2) + idx]);
            float ca = cas[c];
            float v0 = f.x * ca, v1 = f.y * ca;
            s0 += v0; s1 += v1;
            m0 = fmaxf(m0, v0); m1 = fmaxf(m1, v1);
        }
        int p0 = idx * 2, p1 = p0 + 1;
        int r0 = p0 / WW, cc0 = p0 % WW, r1 = p1 / WW, cc1 = p1 % WW;
        tile[(r0 + 3) * 26 + cc0 + 3] = s0 * (1.f / 64.f);
        tile[(r1 + 3) * 26 + cc1 + 3] = s1 * (1.f / 64.f);
        tile[140 * 26 + (r0 + 3) * 26 + cc0 + 3] = m0;
        tile[140 * 26 + (r1 + 3) * 26 + cc1 + 3] = m1;
    }
    __syncthreads();
    float Sacc = 0.f;
    for (int p = tid; p < HWS; p += 256) {
        int r = p / WW, c = p % WW;
        float acc = 0.f;
#pragma unroll
        for (int ch = 0; ch < 2; ch++)
            for (int dr = 0; dr < 7; dr++)
#pragma unroll
                for (int dc = 0; dc < 7; dc++)
                    acc = fmaf(wts[ch * 49 + dr * 7 + dc],
                               tile[ch * 140 * 26 + (r + dr) * 26 + c + dc], acc);
        float sa = 1.f / (1.f + __expf(-acc));
        g_sa[b * HWS + p] = sa;
        Sacc += sa * tile[(r + 3) * 26 + c + 3];   // sp_mean at p
    }
    red[tid] = Sacc;
    __syncthreads();
    if (tid < 8) {
        float s = 0.f;
        for (int i = tid; i < 256; i += 8) s += red[i];   // p%8 == tid%8
        g_S[b * 8 + tid] = s * 64.f;
    }
}

// One routing pass, fused with routing math (warp 0 prologue/epilogue).
// pass 0: d = d(iter1 from S); accumulate T0; write g_T0.
// pass 1: d = d(iter2 from S,T0); accumulate T1; write capsule lengths.
// grid(BB) x 1024; warp w handles channels w and w+32; lane handles capsule k.
__global__ __launch_bounds__(1024) void k_tpass(const float* __restrict__ cW,
                                                float* __restrict__ out, int pass) {
    int b = blockIdx.x;
    __shared__ float sas[HWS];
    __shared__ float dsm[8];
    __shared__ float avec[16];
    __shared__ float Tsm[32 * 8];
    int tid = threadIdx.x, warp = tid >> 5, lane = tid & 31;

    for (int i = tid; i < HWS; i += 1024) sas[i] = g_sa[b * HWS + i];

    if (warp == 0) {
        int t = lane, j = t >> 4;
        float Wc[8], S[8];
#pragma unroll
        for (int e = 0; e < 8; e++) { Wc[e] = cW[e * 32 + t]; S[e] = g_S[b * 8 + e]; }
        // ---- iter-1 math (uniform coupling): te = S/2 ----
        float s = 0.f;
#pragma unroll
        for (int e = 0; e < 8; e++) s = fmaf(0.5f * S[e], Wc[e], s);
        float ss = s * s;
#pragma unroll
        for (int o = 8; o > 0; o >>= 1) ss += __shfl_xor_sync(~0u, ss, o);
        ss += EPSV;
        float v = (sqrtf(ss) / (1.f + ss)) * s;
#pragma unroll
        for (int e = 0; e < 8; e++) {
            float pa = Wc[e] * v;
#pragma unroll
            for (int o = 8; o > 0; o >>= 1) pa += __shfl_xor_sync(~0u, pa, o);
            if ((t & 15) == e) avec[j * 8 + e] = pa;
        }
        __syncwarp();
        if (pass == 1) {
            // ---- iter-2 math: te from T0 ----
            float s2 = 0.f;
#pragma unroll
            for (int e = 0; e < 8; e++) {
                float T0 = g_T0[b * 8 + e];
                float te = (j == 0) ? T0 : S[e] - T0;
                s2 = fmaf(te, Wc[e], s2);
            }
            float ss2 = s2 * s2;
#pragma unroll
            for (int o = 8; o > 0; o >>= 1) ss2 += __shfl_xor_sync(~0u, ss2, o);
            ss2 += EPSV;
            float v2 = (sqrtf(ss2) / (1.f + ss2)) * s2;
#pragma unroll
            for (int e = 0; e < 8; e++) {
                float pa = Wc[e] * v2;
#pragma unroll
                for (int o = 8; o > 0; o >>= 1) pa += __shfl_xor_sync(~0u, pa, o);
                if ((t & 15) == e) avec[j * 8 + e] += pa;
            }
            __syncwarp();
        }
        if (t < 8) dsm[t] = avec[t] - avec[8 + t];
    }
    __syncthreads();

    float d[8], Te[8];
#pragma unroll
    for (int e = 0; e < 8; e++) { d[e] = dsm[e]; Te[e] = 0.f; }

    const uint4* hb = (const uint4*)(g_h + (size_t)b * CC * HWS);  // 8 halves per k
#pragma unroll
    for (int rep = 0; rep < 2; rep++) {
        int c = warp + rep * 32;
        float ca = __ldg(&g_ca[b * 64 + c]);
        const uint4* hc = hb + (size_t)c * NK;
#pragma unroll
        for (int it = 0; it < 11; it++) {
            int k = it * 32 + lane;
            if (k < NK) {
                uint4 raw = hc[k];
                const __half2* hp = (const __half2*)&raw;
                float u[8], us[8];
                float2 f0 = __half22float2(hp[0]), f1 = __half22float2(hp[1]);
                float2 f2 = __half22float2(hp[2]), f3 = __half22float2(hp[3]);
                u[0] = f0.x; u[1] = f0.y; u[2] = f1.x; u[3] = f1.y;
                u[4] = f2.x; u[5] = f2.y; u[6] = f3.x; u[7] = f3.y;
                float dx = 0.f;
#pragma unroll
                for (int e = 0; e < 8; e++) {
                    us[e] = u[e] * sas[8 * k + e];
                    dx = fmaf(us[e], d[e], dx);
                }
                dx *= ca;
                float sg = ca / (1.f + __expf(-dx));
#pragma unroll
                for (int e = 0; e < 8; e++) Te[e] = fmaf(sg, us[e], Te[e]);
            }
        }
    }
#pragma unroll
    for (int e = 0; e < 8; e++)
#pragma unroll
        for (int o = 16; o > 0; o >>= 1) Te[e] += __shfl_xor_sync(~0u, Te[e], o);
    if (lane == 0)
#pragma unroll
        for (int e = 0; e < 8; e++) Tsm[warp * 8 + e] = Te[e];
    __syncthreads();

    if (warp == 0) {
        float part[8];
#pragma unroll
        for (int e = 0; e < 8; e++) part[e] = Tsm[lane * 8 + e];
#pragma unroll
        for (int e = 0; e < 8; e++)
#pragma unroll
            for (int o = 16; o > 0; o >>= 1) part[e] += __shfl_xor_sync(~0u, part[e], o);
        if (lane == 0)
#pragma unroll
            for (int e = 0; e < 8; e++) Tsm[e] = part[e];
        __syncwarp();

        if (pass == 0) {
            if (lane < 8) g_T0[b * 8 + lane] = Tsm[lane];
        } else {
            // ---- iter-3 math: lengths from T1 ----
            int t = lane, j = t >> 4;
            float s = 0.f;
#pragma unroll
            for (int e = 0; e < 8; e++) {
                float T1 = Tsm[e];
                float te = (j == 0) ? T1 : g_S[b * 8 + e] - T1;
                s = fmaf(te, cW[e * 32 + t], s);
            }
            float ss = s * s;
#pragma unroll
            for (int o = 8; o > 0; o >>= 1) ss += __shfl_xor_sync(~0u, ss, o);
            ss += EPSV;
            float v = (sqrtf(ss) / (1.f + ss)) * s;
            float vs = v * v;
#pragma unroll
            for (int o = 8; o > 0; o >>= 1) vs += __shfl_xor_sync(~0u, vs, o);
            if ((t & 15) == 0) out[b * 2 + j] = sqrtf(vs + EPSV);
        }
    }
}

extern "C" void kernel_launch(void* const* d_in, const int* in_sizes, int n_in,
                              void* d_out, int out_size) {
    const float* x   = (const float*)d_in[0];
    const float* cw  = (const float*)d_in[1];
    const float* cb  = (const float*)d_in[2];
    const float* w1  = (const float*)d_in[3];
    const float* w2  = (const float*)d_in[4];
    const float* sw  = (const float*)d_in[5];
    const float* cpW = (const float*)d_in[6];
    float* out = (float*)d_out;

    k_conv<<<BB, 256>>>(x, cw, cb, w1, w2);
    k_spa<<<BB, 256>>>(sw);
    k_tpass<<<BB, 1024>>>(cpW, out, 0);
    k_tpass<<<BB, 1024>>>(cpW, out, 1);
}

// round 13
// speedup vs baseline: 1.4700x; 1.0461x over previous
#include <cuda_runtime.h>
#include <cuda_fp16.h>
#include <math.h>

#define BB 128
#define CC 64
#define HH 134
#define WW 20
#define HWS 2680
#define NK 335
#define EPSV 1e-8f

__device__ __align__(16) __half g_h [(size_t)BB*CC*HWS];  // relu(conv(x)) [b][c][hw]
__device__ __align__(16) __half g_sa[BB*HWS];             // spatial attention (half)
__device__ float g_ca[BB*CC];
__device__ float g_S [BB*8];
__device__ float g_T0[BB*8];

// conv3x3 + relu + per-(b,c) sum/max + CBAM channel-attention MLP, fused.
// grid(BB) x 256; warp w owns channels [8w, 8w+8); block owns batch b entirely.
__global__ __launch_bounds__(256) void k_conv(const float* __restrict__ x,
                                              const float* __restrict__ cw,
                                              const float* __restrict__ cb,
                                              const float* __restrict__ w1,
                                              const float* __restrict__ w2) {
    int b = blockIdx.x;
    __shared__ float tile[136 * 22];                // full image + 1-halo
    __shared__ float avg[64], mxv[64], hid[8];
    const float* xb = x + b * HWS;
    for (int i = threadIdx.x; i < 136 * 22; i += 256) {
        int rr = i / 22 - 1, cc = i % 22 - 1;
        tile[i] = (rr >= 0 && rr < HH && cc >= 0 && cc < WW) ? xb[rr * WW + cc] : 0.f;
    }
    __syncthreads();
    int warp = threadIdx.x >> 5, lane = threadIdx.x & 31, c0 = warp * 8;
    float w[8][9], bias[8], sum[8], mx[8];
#pragma unroll
    for (int j = 0; j < 8; j++) {
#pragma unroll
        for (int t = 0; t < 9; t++) w[j][t] = __ldg(&cw[(c0 + j) * 9 + t]);
        bias[j] = __ldg(&cb[c0 + j]);
        sum[j] = 0.f; mx[j] = 0.f;
    }
    for (int p = lane; p < HWS; p += 32) {
        int lr = p / WW, col = p % WW;
        float win[9];
#pragma unroll
        for (int dr = 0; dr < 3; dr++)
#pragma unroll
            for (int dc = 0; dc < 3; dc++) win[dr * 3 + dc] = tile[(lr + dr) * 22 + col + dc];
#pragma unroll
        for (int j = 0; j < 8; j++) {
            float acc = bias[j];
#pragma unroll
            for (int t = 0; t < 9; t++) acc = fmaf(w[j][t], win[t], acc);
            acc = fmaxf(acc, 0.f);
            g_h[((size_t)b * CC + c0 + j) * HWS + p] = __float2half(acc);
            sum[j] += acc; mx[j] = fmaxf(mx[j], acc);
        }
    }
#pragma unroll
    for (int j = 0; j < 8; j++)
#pragma unroll
        for (int o = 16; o > 0; o >>= 1) {
            sum[j] += __shfl_xor_sync(~0u, sum[j], o);
            mx[j] = fmaxf(mx[j], __shfl_xor_sync(~0u, mx[j], o));
        }
    if (lane == 0)
#pragma unroll
        for (int j = 0; j < 8; j++) {
            avg[c0 + j] = sum[j] * (1.f / HWS);
            mxv[c0 + j] = mx[j];
        }
    __syncthreads();
    int t = threadIdx.x;
    if (t < 8) {
        const float* v = (t < 4) ? avg : mxv;
        int i = t & 3;
        float acc = 0.f;
        for (int c = 0; c < 64; c++) acc += v[c] * __ldg(&w1[i * 64 + c]);
        hid[t] = fmaxf(acc, 0.f);
    }
    __syncthreads();
    if (t < 64) {
        float o = 0.f;
#pragma unroll
        for (int i = 0; i < 4; i++) o += (hid[i] + hid[4 + i]) * __ldg(&w2[t * 4 + i]);
        g_ca[b * 64 + t] = 1.f / (1.f + __expf(-o));
    }
}

// per-pixel channel mean/max of h*ca + 7x7 conv + sigmoid -> g_sa (half);
// accumulate S_e (from the quantized sa, for identity consistency).
// grid(BB) x 256
__global__ __launch_bounds__(256) void k_spa(const float* __restrict__ sw) {
    int b = blockIdx.x;
    __shared__ float tile[2 * 140 * 26];
    __shared__ float wts[98];
    __shared__ float cas[64];
    __shared__ float red[256];
    int tid = threadIdx.x;
    if (tid < 98) wts[tid] = sw[tid];
    if (tid < 64) cas[tid] = g_ca[b * 64 + tid];
    for (int i = tid; i < 2 * 140 * 26; i += 256) tile[i] = 0.f;
    __syncthreads();
    const __half2* hb = (const __half2*)(g_h + (size_t)b * CC * HWS);
    for (int idx = tid; idx < HWS / 2; idx += 256) {
        float s0 = 0.f, s1 = 0.f, m0 = 0.f, m1 = 0.f;
#pragma unroll 8
        for (int c = 0; c < 64; c++) {
            float2 f = __half22float2(hb[c * (HWS / 2) + idx]);
            float ca = cas[c];
            float v0 = f.x * ca, v1 = f.y * ca;
            s0 += v0; s1 += v1;
            m0 = fmaxf(m0, v0); m1 = fmaxf(m1, v1);
        }
        int p0 = idx * 2, p1 = p0 + 1;
        int r0 = p0 / WW, cc0 = p0 % WW, r1 = p1 / WW, cc1 = p1 % WW;
        tile[(r0 + 3) * 26 + cc0 + 3] = s0 * (1.f / 64.f);
        tile[(r1 + 3) * 26 + cc1 + 3] = s1 * (1.f / 64.f);
        tile[140 * 26 + (r0 + 3) * 26 + cc0 + 3] = m0;
        tile[140 * 26 + (r1 + 3) * 26 + cc1 + 3] = m1;
    }
    __syncthreads();
    float Sacc = 0.f;
    for (int p = tid; p < HWS; p += 256) {
        int r = p / WW, c = p % WW;
        float acc = 0.f;
#pragma unroll
        for (int ch = 0; ch < 2; ch++)
            for (int dr = 0; dr < 7; dr++)
#pragma unroll
                for (int dc = 0; dc < 7; dc++)
                    acc = fmaf(wts[ch * 49 + dr * 7 + dc],
                               tile[ch * 140 * 26 + (r + dr) * 26 + c + dc], acc);
        float sa = __fdividef(1.f, 1.f + __expf(-acc));
        __half sah = __float2half(sa);
        g_sa[b * HWS + p] = sah;
        Sacc += __half2float(sah) * tile[(r + 3) * 26 + c + 3];   // sp_mean at p
    }
    red[tid] = Sacc;
    __syncthreads();
    if (tid < 8) {
        float s = 0.f;
        for (int i = tid; i < 256; i += 8) s += red[i];   // p%8 == tid%8
        g_S[b * 8 + tid] = s * 64.f;
    }
}

// One routing pass, routing math replicated per-warp (no prologue barrier).
// pass 0: d = d(iter1 from S); accumulate T0; write g_T0.
// pass 1: d = d(iter2 from S,T0); accumulate T1; write capsule lengths.
// grid(BB) x 1024; warp w handles channels w and w+32; lane handles capsule k.
__global__ __launch_bounds__(1024) void k_tpass(const float* __restrict__ cW,
                                                float* __restrict__ out, int pass) {
    int b = blockIdx.x;
    __shared__ float Tsm[32 * 8];
    int tid = threadIdx.x, warp = tid >> 5, lane = tid & 31;
    int jg = lane >> 4;                    // capsule group of this lane (0/1)

    // ---- routing math, computed redundantly by EVERY warp ----
    float d[8];
    {
        float Wc[8], S[8], acc[8];
#pragma unroll
        for (int e = 0; e < 8; e++) {
            Wc[e] = __ldg(&cW[e * 32 + lane]);
            S[e]  = __ldg(&g_S[b * 8 + e]);
        }
        // iter-1 (uniform coupling): te = S/2
        float s = 0.f;
#pragma unroll
        for (int e = 0; e < 8; e++) s = fmaf(0.5f * S[e], Wc[e], s);
        float ss = s * s;
#pragma unroll
        for (int o = 8; o > 0; o >>= 1) ss += __shfl_xor_sync(~0u, ss, o);
        ss += EPSV;
        float v = (sqrtf(ss) / (1.f + ss)) * s;
#pragma unroll
        for (int e = 0; e < 8; e++) {
            float pa = Wc[e] * v;
#pragma unroll
            for (int o = 8; o > 0; o >>= 1) pa += __shfl_xor_sync(~0u, pa, o);
            acc[e] = pa;                   // all lanes of group j hold a_j[e]
        }
        if (pass == 1) {
            float s2 = 0.f;
#pragma unroll
            for (int e = 0; e < 8; e++) {
                float T0 = __ldg(&g_T0[b * 8 + e]);
                float te = (jg == 0) ? T0 : S[e] - T0;
                s2 = fmaf(te, Wc[e], s2);
            }
            float ss2 = s2 * s2;
#pragma unroll
            for (int o = 8; o > 0; o >>= 1) ss2 += __shfl_xor_sync(~0u, ss2, o);
            ss2 += EPSV;
            float v2 = (sqrtf(ss2) / (1.f + ss2)) * s2;
#pragma unroll
            for (int e = 0; e < 8; e++) {
                float pa = Wc[e] * v2;
#pragma unroll
                for (int o = 8; o > 0; o >>= 1) pa += __shfl_xor_sync(~0u, pa, o);
                acc[e] += pa;
            }
        }
        // d = a0 - a1, uniform across the warp via xor-16 + sign fix
#pragma unroll
        for (int e = 0; e < 8; e++) {
            float diff = acc[e] - __shfl_xor_sync(~0u, acc[e], 16);
            d[e] = jg ? -diff : diff;
        }
    }

    // ---- main loop: T_e += sigmoid(u.d) * u_e over this warp's channels ----
    float Te[8];
#pragma unroll
    for (int e = 0; e < 8; e++) Te[e] = 0.f;

    const uint4* hb  = (const uint4*)(g_h  + (size_t)b * CC * HWS);  // 8 halves/k
    const uint4* sab = (const uint4*)(g_sa + (size_t)b * HWS);       // 8 halves/k
#pragma unroll
    for (int rep = 0; rep < 2; rep++) {
        int c = warp + rep * 32;
        float ca = __ldg(&g_ca[b * 64 + c]);
        const uint4* hc = hb + (size_t)c * NK;
#pragma unroll
        for (int it = 0; it < 11; it++) {
            int k = it * 32 + lane;
            if (k < NK) {
                uint4 raw  = hc[k];
                uint4 sraw = sab[k];
                const __half2* hp = (const __half2*)&raw;
                const __half2* sp = (const __half2*)&sraw;
                float us[8];
                float dx = 0.f;
#pragma unroll
                for (int q = 0; q < 4; q++) {
                    float2 uf = __half22float2(hp[q]);
                    float2 sf = __half22float2(sp[q]);
                    us[2 * q]     = uf.x * sf.x;
                    us[2 * q + 1] = uf.y * sf.y;
                    dx = fmaf(us[2 * q],     d[2 * q],     dx);
                    dx = fmaf(us[2 * q + 1], d[2 * q + 1], dx);
                }
                dx *= ca;
                float sg = __fdividef(ca, 1.f + __expf(-dx));
#pragma unroll
                for (int e = 0; e < 8; e++) Te[e] = fmaf(sg, us[e], Te[e]);
            }
        }
    }
#pragma unroll
    for (int e = 0; e < 8; e++)
#pragma unroll
        for (int o = 16; o > 0; o >>= 1) Te[e] += __shfl_xor_sync(~0u, Te[e], o);
    if (lane == 0)
#pragma unroll
        for (int e = 0; e < 8; e++) Tsm[warp * 8 + e] = Te[e];
    __syncthreads();

    if (warp == 0) {
        float part[8];
#pragma unroll
        for (int e = 0; e < 8; e++) part[e] = Tsm[lane * 8 + e];
#pragma unroll
        for (int e = 0; e < 8; e++)
#pragma unroll
            for (int o = 16; o > 0; o >>= 1) part[e] += __shfl_xor_sync(~0u, part[e], o);
        if (lane == 0)
#pragma unroll
            for (int e = 0; e < 8; e++) Tsm[e] = part[e];
        __syncwarp();

        if (pass == 0) {
            if (lane < 8) g_T0[b * 8 + lane] = Tsm[lane];
        } else {
            // iter-3 math: lengths from T1
            float s = 0.f;
#pragma unroll
            for (int e = 0; e < 8; e++) {
                float T1 = Tsm[e];
                float te = (jg == 0) ? T1 : __ldg(&g_S[b * 8 + e]) - T1;
                s = fmaf(te, __ldg(&cW[e * 32 + lane]), s);
            }
            float ss = s * s;
#pragma unroll
            for (int o = 8; o > 0; o >>= 1) ss += __shfl_xor_sync(~0u, ss, o);
            ss += EPSV;
            float v = (sqrtf(ss) / (1.f + ss)) * s;
            float vs = v * v;
#pragma unroll
            for (int o = 8; o > 0; o >>= 1) vs += __shfl_xor_sync(~0u, vs, o);
            if ((lane & 15) == 0) out[b * 2 + jg] = sqrtf(vs + EPSV);
        }
    }
}

extern "C" void kernel_launch(void* const* d_in, const int* in_sizes, int n_in,
                              void* d_out, int out_size) {
    const float* x   = (const float*)d_in[0];
    const float* cw  = (const float*)d_in[1];
    const float* cb  = (const float*)d_in[2];
    const float* w1  = (const float*)d_in[3];
    const float* w2  = (const float*)d_in[4];
    const float* sw  = (const float*)d_in[5];
    const float* cpW = (const float*)d_in[6];
    float* out = (float*)d_out;

    k_conv<<<BB, 256>>>(x, cw, cb, w1, w2);
    k_spa<<<BB, 256>>>(sw);
    k_tpass<<<BB, 1024>>>(cpW, out, 0);
    k_tpass<<<BB, 1024>>>(cpW, out, 1);
}